// round 16
// baseline (speedup 1.0000x reference)
#include <cuda_runtime.h>
#include <cuda_fp16.h>
#include <math.h>
#include <stdint.h>

// ---------------------------------------------------------------------------
// Transformer block: B=16, S=512, D=1024, H=16, HD=64, FF=4096
// FP16 mma.sync.m16n8k16 + ldmatrix.x4 (.trans for B), fp32 accumulate,
// BK=64 / 3-stage cp.async GEMM (BM=128 and BM=256 variants), fused QKV,
// natural [K,N] weights, flash attention (exp2 softmax), side-stream
// prologue, half residual spine, warp-per-row LN, MUFU.TANH gelu.
// ---------------------------------------------------------------------------

#define BATCH   16
#define SEQ     512
#define DMODEL  1024
#define NHEAD   16
#define HDIM    64
#define FFDIM   4096
#define ROWS    (BATCH * SEQ)          // 8192
#define QKVLD   (3 * DMODEL)           // 3072

// half residual spine
__device__ __half g_x1 [ROWS * DMODEL];
__device__ __half g_x2 [ROWS * DMODEL];
// half operands
__device__ __half g_c   [ROWS * DMODEL];
__device__ __half g_qkv [(size_t)ROWS * QKVLD];
__device__ __half g_at  [ROWS * DMODEL];
__device__ __half g_h   [ROWS * FFDIM];
// half weights (natural [K,N] layout)
__device__ __half g_wqkv[(size_t)DMODEL * QKVLD];            // wq*0.125*log2e | wk | wv
__device__ __half g_woh [DMODEL * DMODEL];
__device__ __half g_w1h [(size_t)DMODEL * FFDIM];
__device__ __half g_w2h [(size_t)DMODEL * FFDIM];

// ---------------------------------------------------------------------------
__device__ __forceinline__ float tanh_fast(float x) {
    float r;
    asm("tanh.approx.f32 %0, %1;" : "=f"(r) : "f"(x));
    return r;
}
__device__ __forceinline__ float exp2_fast(float x) {
    float r;
    asm("ex2.approx.f32 %0, %1;" : "=f"(r) : "f"(x));
    return r;
}

__device__ __forceinline__ float gelu_tanh(float x) {
    float x3 = x * x * x;
    float u  = 0.7978845608028654f * (x + 0.044715f * x3);
    return 0.5f * x * (1.0f + tanh_fast(u));
}

__device__ __forceinline__ void mma_f16(float* c, const uint32_t* a, const uint32_t* b) {
    asm volatile(
        "mma.sync.aligned.m16n8k16.row.col.f32.f16.f16.f32 "
        "{%0,%1,%2,%3}, {%4,%5,%6,%7}, {%8,%9}, {%0,%1,%2,%3};\n"
        : "+f"(c[0]), "+f"(c[1]), "+f"(c[2]), "+f"(c[3])
        : "r"(a[0]), "r"(a[1]), "r"(a[2]), "r"(a[3]),
          "r"(b[0]), "r"(b[1]));
}

__device__ __forceinline__ void ldm_x4(uint32_t* r, uint32_t addr) {
    asm volatile(
        "ldmatrix.sync.aligned.m8n8.x4.shared.b16 {%0,%1,%2,%3}, [%4];"
        : "=r"(r[0]), "=r"(r[1]), "=r"(r[2]), "=r"(r[3]) : "r"(addr));
}
__device__ __forceinline__ void ldm_x4_t(uint32_t* r, uint32_t addr) {
    asm volatile(
        "ldmatrix.sync.aligned.m8n8.x4.trans.shared.b16 {%0,%1,%2,%3}, [%4];"
        : "=r"(r[0]), "=r"(r[1]), "=r"(r[2]), "=r"(r[3]) : "r"(addr));
}

__device__ __forceinline__ void cp16(uint32_t dst, const void* src) {
    asm volatile("cp.async.cg.shared.global [%0], [%1], 16;\n" :: "r"(dst), "l"(src));
}
__device__ __forceinline__ void cp_commit() {
    asm volatile("cp.async.commit_group;\n");
}
template<int N>
__device__ __forceinline__ void cp_wait() {
    asm volatile("cp.async.wait_group %0;\n" :: "n"(N));
}

__device__ __forceinline__ uint32_t packh2(float a, float b) {
    __half2 h = __floats2half2_rn(a, b);
    return *(uint32_t*)&h;
}

__device__ __forceinline__ float4 load4(const float* p, int idx) {
    return ((const float4*)p)[idx];
}
__device__ __forceinline__ float4 load4(const __half* p, int idx) {
    __half2 a = ((const __half2*)p)[idx * 2];
    __half2 b = ((const __half2*)p)[idx * 2 + 1];
    return make_float4(__low2float(a), __high2float(a),
                       __low2float(b), __high2float(b));
}

// ---------------------------------------------------------------------------
// cvt: fp32 -> fp16 straight copy
// ---------------------------------------------------------------------------
__global__ void cvt_h(const float* __restrict__ in, __half* __restrict__ out, int n4) {
    int i = blockIdx.x * blockDim.x + threadIdx.x;
    if (i < n4) {
        float4 v = ((const float4*)in)[i];
        ((__half2*)out)[i * 2]     = __floats2half2_rn(v.x, v.y);
        ((__half2*)out)[i * 2 + 1] = __floats2half2_rn(v.z, v.w);
    }
}

// cvt QKV: interleave wq*(0.125*log2e)|wk|wv into [K=1024, N=3072]
#define QSCALE (0.125f * 1.44269504088896341f)
__global__ void cvt_qkv(const float* __restrict__ wq, const float* __restrict__ wk,
                        const float* __restrict__ wv, __half* __restrict__ out) {
    int i = blockIdx.x * blockDim.x + threadIdx.x;
    int row = i >> 8;
    int c4  = i & 255;
    float4 a = ((const float4*)wq)[i];
    float4 b = ((const float4*)wk)[i];
    float4 c = ((const float4*)wv)[i];
    __half2* o = (__half2*)(out + (size_t)row * QKVLD);
    o[c4 * 2]            = __floats2half2_rn(a.x * QSCALE, a.y * QSCALE);
    o[c4 * 2 + 1]        = __floats2half2_rn(a.z * QSCALE, a.w * QSCALE);
    o[512 + c4 * 2]      = __floats2half2_rn(b.x, b.y);
    o[512 + c4 * 2 + 1]  = __floats2half2_rn(b.z, b.w);
    o[1024 + c4 * 2]     = __floats2half2_rn(c.x, c.y);
    o[1024 + c4 * 2 + 1] = __floats2half2_rn(c.z, c.w);
}

// ---------------------------------------------------------------------------
// LayerNorm, warp-per-row (8 rows/block, shfl-only). TIN float or half.
// ---------------------------------------------------------------------------
template<typename TIN>
__global__ void ln_kernel(const TIN* __restrict__ x,
                          const float* __restrict__ scale,
                          __half* __restrict__ out) {
    int warp = threadIdx.x >> 5, lane = threadIdx.x & 31;
    int row  = blockIdx.x * 8 + warp;
    const TIN* xr = x + (size_t)row * DMODEL;

    float4 v[8];
    float s = 0.f, q = 0.f;
    #pragma unroll
    for (int j = 0; j < 8; j++) {
        v[j] = load4(xr + j * 128, lane);
        s += v[j].x + v[j].y + v[j].z + v[j].w;
        q += v[j].x * v[j].x + v[j].y * v[j].y + v[j].z * v[j].z + v[j].w * v[j].w;
    }
    #pragma unroll
    for (int o = 16; o > 0; o >>= 1) {
        s += __shfl_xor_sync(0xffffffffu, s, o);
        q += __shfl_xor_sync(0xffffffffu, q, o);
    }
    float mean = s * (1.0f / DMODEL);
    float var  = q * (1.0f / DMODEL) - mean * mean;
    float r    = rsqrtf(var + 1e-6f);

    __half* orow = out + (size_t)row * DMODEL;
    #pragma unroll
    for (int j = 0; j < 8; j++) {
        float4 sc = ((const float4*)scale)[j * 32 + lane];
        __half2 o0 = __floats2half2_rn((v[j].x - mean) * r * sc.x, (v[j].y - mean) * r * sc.y);
        __half2 o1 = __floats2half2_rn((v[j].z - mean) * r * sc.z, (v[j].w - mean) * r * sc.w);
        __half2* op = (__half2*)(orow + j * 128 + lane * 4);
        op[0] = o0; op[1] = o1;
    }
}

// ---------------------------------------------------------------------------
// Fused flash attention, double-buffered K/V, exp2-domain softmax.
// grid = (S/128, B*H), 256 threads, 2 CTA/SM; q pre-scaled by 0.125*log2e.
// ---------------------------------------------------------------------------
#define QS_STRIDE 72
#define KS_STRIDE 72
#define VS_STRIDE 72
#define CHUNK     128
#define FA_SMEM_H (128 * QS_STRIDE + 2 * 2 * CHUNK * KS_STRIDE)

__global__ void __launch_bounds__(256, 2)
flash_kernel(const __half* __restrict__ qkv, __half* __restrict__ at) {
    extern __shared__ __half sm[];
    __half* Qs = sm;
    __half* KVs = Qs + 128 * QS_STRIDE;

    int bh = blockIdx.y;
    int b  = bh >> 4;
    int h  = bh & 15;
    int i0 = blockIdx.x * 128;

    const __half* Qg = qkv + ((size_t)(b * SEQ + i0)) * QKVLD + h * HDIM;
    const __half* Kg = qkv + ((size_t)(b * SEQ))      * QKVLD + DMODEL     + h * HDIM;
    const __half* Vg = qkv + ((size_t)(b * SEQ))      * QKVLD + 2 * DMODEL + h * HDIM;

    int tid = threadIdx.x;
    uint32_t Qsb  = (uint32_t)__cvta_generic_to_shared(Qs);
    uint32_t KVsb = (uint32_t)__cvta_generic_to_shared(KVs);
    const uint32_t STAGE_B = (uint32_t)(2 * CHUNK * KS_STRIDE) * 2u;
    const uint32_t VOFF_B  = (uint32_t)(CHUNK * KS_STRIDE) * 2u;

    auto load_chunk = [&](int jc, int stg) {
        const __half* Kc = Kg + (size_t)(jc * CHUNK) * QKVLD;
        const __half* Vc = Vg + (size_t)(jc * CHUNK) * QKVLD;
        uint32_t base = KVsb + (uint32_t)stg * STAGE_B;
        #pragma unroll
        for (int i = 0; i < 4; i++) {
            int idx = tid + i * 256;
            int r = idx >> 3, c = idx & 7;
            cp16(base + (uint32_t)(r * KS_STRIDE + c * 8) * 2u, Kc + (size_t)r * QKVLD + c * 8);
        }
        #pragma unroll
        for (int i = 0; i < 4; i++) {
            int idx = tid + i * 256;
            int r = idx >> 3, c = idx & 7;
            cp16(base + VOFF_B + (uint32_t)(r * VS_STRIDE + c * 8) * 2u, Vc + (size_t)r * QKVLD + c * 8);
        }
    };

    #pragma unroll
    for (int i = 0; i < 4; i++) {
        int idx = tid + i * 256;
        int r = idx >> 3, c = idx & 7;
        cp16(Qsb + (uint32_t)(r * QS_STRIDE + c * 8) * 2u, Qg + (size_t)r * QKVLD + c * 8);
    }
    load_chunk(0, 0);
    cp_commit();

    int warp = tid >> 5, lane = tid & 31;
    int g = lane >> 2, tc = lane & 3;
    int wr = warp * 16;
    int lane16 = lane & 15, laneHi = lane >> 4;
    int bRow   = laneHi * 8 + (lane & 7);
    int bKoff  = ((lane >> 3) & 1) * 8;
    int tRow   = (lane & 7) + ((lane >> 3) & 1) * 8;
    int tNoff  = laneHi * 8;

    uint32_t qLdm  = Qsb  + (uint32_t)((wr + lane16) * QS_STRIDE + laneHi * 8) * 2u;
    uint32_t kLdm0 = KVsb + (uint32_t)(bRow * KS_STRIDE + bKoff) * 2u;
    uint32_t vLdm0 = KVsb + VOFF_B + (uint32_t)(tRow * VS_STRIDE + tNoff) * 2u;

    float m0 = -1e30f, m1 = -1e30f, l0 = 0.f, l1 = 0.f;
    float O[8][4];
    #pragma unroll
    for (int dt = 0; dt < 8; dt++)
        #pragma unroll
        for (int e = 0; e < 4; e++) O[dt][e] = 0.f;

    #pragma unroll
    for (int jc = 0; jc < 4; jc++) {
        if (jc < 3) { load_chunk(jc + 1, (jc + 1) & 1); }
        cp_commit();
        if (jc < 3) cp_wait<1>(); else cp_wait<0>();
        __syncthreads();

        uint32_t stOff = (uint32_t)(jc & 1) * STAGE_B;
        uint32_t kLdm = kLdm0 + stOff;
        uint32_t vLdm = vLdm0 + stOff;

        float S[16][4];
        #pragma unroll
        for (int nt = 0; nt < 16; nt++)
            #pragma unroll
            for (int e = 0; e < 4; e++) S[nt][e] = 0.f;

        #pragma unroll
        for (int ks = 0; ks < 4; ks++) {
            uint32_t a[4];
            ldm_x4(a, qLdm + (uint32_t)(ks * 16) * 2u);
            #pragma unroll
            for (int p = 0; p < 8; p++) {
                uint32_t bb[4];
                ldm_x4(bb, kLdm + (uint32_t)((p * 16) * KS_STRIDE + ks * 16) * 2u);
                mma_f16(S[2*p    ], a, bb);
                mma_f16(S[2*p + 1], a, bb + 2);
            }
        }

        // online softmax (log2 domain: scores already scaled by log2e)
        float mx0 = -1e30f, mx1 = -1e30f;
        #pragma unroll
        for (int nt = 0; nt < 16; nt++) {
            mx0 = fmaxf(mx0, fmaxf(S[nt][0], S[nt][1]));
            mx1 = fmaxf(mx1, fmaxf(S[nt][2], S[nt][3]));
        }
        mx0 = fmaxf(mx0, __shfl_xor_sync(0xffffffffu, mx0, 1));
        mx0 = fmaxf(mx0, __shfl_xor_sync(0xffffffffu, mx0, 2));
        mx1 = fmaxf(mx1, __shfl_xor_sync(0xffffffffu, mx1, 1));
        mx1 = fmaxf(mx1, __shfl_xor_sync(0xffffffffu, mx1, 2));
        float mn0 = fmaxf(m0, mx0), mn1 = fmaxf(m1, mx1);
        float al0 = exp2_fast(m0 - mn0), al1 = exp2_fast(m1 - mn1);
        m0 = mn0; m1 = mn1;

        float rs0 = 0.f, rs1 = 0.f;
        #pragma unroll
        for (int nt = 0; nt < 16; nt++) {
            S[nt][0] = exp2_fast(S[nt][0] - mn0);
            S[nt][1] = exp2_fast(S[nt][1] - mn0);
            S[nt][2] = exp2_fast(S[nt][2] - mn1);
            S[nt][3] = exp2_fast(S[nt][3] - mn1);
            rs0 += S[nt][0] + S[nt][1];
            rs1 += S[nt][2] + S[nt][3];
        }
        rs0 += __shfl_xor_sync(0xffffffffu, rs0, 1);
        rs0 += __shfl_xor_sync(0xffffffffu, rs0, 2);
        rs1 += __shfl_xor_sync(0xffffffffu, rs1, 1);
        rs1 += __shfl_xor_sync(0xffffffffu, rs1, 2);
        l0 = l0 * al0 + rs0;
        l1 = l1 * al1 + rs1;

        #pragma unroll
        for (int dt = 0; dt < 8; dt++) {
            O[dt][0] *= al0; O[dt][1] *= al0;
            O[dt][2] *= al1; O[dt][3] *= al1;
        }

        #pragma unroll
        for (int kp = 0; kp < 8; kp++) {
            uint32_t a[4];
            a[0] = packh2(S[2*kp  ][0], S[2*kp  ][1]);
            a[1] = packh2(S[2*kp  ][2], S[2*kp  ][3]);
            a[2] = packh2(S[2*kp+1][0], S[2*kp+1][1]);
            a[3] = packh2(S[2*kp+1][2], S[2*kp+1][3]);
            #pragma unroll
            for (int p = 0; p < 4; p++) {
                uint32_t bb[4];
                ldm_x4_t(bb, vLdm + (uint32_t)((kp * 16) * VS_STRIDE + p * 16) * 2u);
                mma_f16(O[2*p    ], a, bb);
                mma_f16(O[2*p + 1], a, bb + 2);
            }
        }
        __syncthreads();
    }

    float inv0 = 1.0f / l0, inv1 = 1.0f / l1;
    int row0 = b * SEQ + i0 + wr + g;
    __half* ob = at + (size_t)row0 * DMODEL + h * HDIM;
    #pragma unroll
    for (int dt = 0; dt < 8; dt++) {
        __half2 o0 = __floats2half2_rn(O[dt][0] * inv0, O[dt][1] * inv0);
        __half2 o1 = __floats2half2_rn(O[dt][2] * inv1, O[dt][3] * inv1);
        *(__half2*)(ob + dt * 8 + tc * 2)                        = o0;
        *(__half2*)(ob + (size_t)8 * DMODEL + dt * 8 + tc * 2)   = o1;
    }
}

// ---------------------------------------------------------------------------
// FP16 GEMM (templated BM), fp32 accumulate, BK=64 / 3-stage cp.async,
// ldmatrix(.trans B).  BM=128: 256 thr (2Mx4N warps), 2 CTA/SM.
//                      BM=256: 512 thr (4Mx4N warps), 1 CTA/SM.
// EPI: 0 none | 1 gelu(acc+bias) | 2 acc+bias+res | 3 res+2*acc
// ---------------------------------------------------------------------------
template<int BM, int EPI, typename OUT, typename RES>
__global__ void __launch_bounds__(BM * 2, 256 / BM)
gemm_kernel(const __half* __restrict__ A, int lda,
            const __half* __restrict__ B, int ldb,
            OUT* __restrict__ C, int ldc,
            const float* __restrict__ bias,
            const RES* __restrict__ res,
            int K) {
    constexpr int BN = 128, BK = 64;
    constexpr int NSTAGES = 3;
    constexpr int NTHREADS = BM * 2;               // 256 or 512
    constexpr int WARPS_M = BM / 64;               // 2 or 4
    constexpr int MT = 4, NT = 4;
    constexpr int ASTRIDE = BK + 8;
    constexpr int BSTRIDE = BN + 8;
    constexpr int A_H = BM * ASTRIDE;
    constexpr int B_H = BK * BSTRIDE;
    constexpr int STAGE_H = A_H + B_H;

    extern __shared__ __half smem[];
    uint32_t smem_u32 = (uint32_t)__cvta_generic_to_shared(smem);

    int m0 = blockIdx.y * BM;
    int n0 = blockIdx.x * BN;

    int tid  = threadIdx.x;
    int warp = tid >> 5, lane = tid & 31;
    int wm = (warp % WARPS_M) * 64;
    int wn = (warp / WARPS_M) * 32;
    int g  = lane >> 2, tc = lane & 3;
    int lane16 = lane & 15, laneHi = lane >> 4;
    int tRow   = (lane & 7) + ((lane >> 3) & 1) * 8;
    int tNoff  = laneHi * 8;

    uint32_t aLdm = smem_u32 + (uint32_t)((wm + lane16) * ASTRIDE + laneHi * 8) * 2u;
    uint32_t bLdm = smem_u32 + (uint32_t)A_H * 2u
                  + (uint32_t)(tRow * BSTRIDE + wn + tNoff) * 2u;

    // loaders: A = BM x 64 halves -> BM*8 cp16; B = 64 x 128 -> 1024 cp16
    int a_r  = tid >> 3;                       // rows per pass = NTHREADS/8
    int a_k8 = (tid & 7) * 8;
    int b_r  = tid >> 4;                       // rows per pass = NTHREADS/16
    int b_c8 = (tid & 15) * 8;
    constexpr int A_ITER = (BM * 8) / NTHREADS;        // 4 (128) or 4 (256)
    constexpr int A_RSTEP = NTHREADS / 8;              // 32 or 64
    constexpr int B_ITER = 1024 / NTHREADS;            // 4 or 2
    constexpr int B_RSTEP = NTHREADS / 16;             // 16 or 32
    const __half* Aptr = A + (size_t)(m0 + a_r) * lda + a_k8;
    const __half* Bptr = B + (size_t)b_r * ldb + n0 + b_c8;

    float acc[MT][NT][4];
    #pragma unroll
    for (int i = 0; i < MT; i++)
        #pragma unroll
        for (int j = 0; j < NT; j++)
            #pragma unroll
            for (int e = 0; e < 4; e++) acc[i][j][e] = 0.f;

    const int ntiles = K / BK;

    auto load_tile = [&](int t, int s) {
        int kt = t * BK;
        uint32_t aBase = smem_u32 + (uint32_t)(s * STAGE_H) * 2u;
        uint32_t bBase = aBase + (uint32_t)A_H * 2u;
        #pragma unroll
        for (int i = 0; i < A_ITER; ++i)
            cp16(aBase + (uint32_t)((a_r + i * A_RSTEP) * ASTRIDE + a_k8) * 2u,
                 Aptr + (size_t)(i * A_RSTEP) * lda + kt);
        #pragma unroll
        for (int i = 0; i < B_ITER; ++i)
            cp16(bBase + (uint32_t)((b_r + i * B_RSTEP) * BSTRIDE + b_c8) * 2u,
                 Bptr + (size_t)(kt + i * B_RSTEP) * ldb);
    };

    #pragma unroll
    for (int s = 0; s < NSTAGES - 1; ++s) {
        if (s < ntiles) load_tile(s, s);
        cp_commit();
    }

    for (int t = 0; t < ntiles; ++t) {
        cp_wait<NSTAGES - 2>();
        __syncthreads();

        int tn = t + NSTAGES - 1;
        if (tn < ntiles) load_tile(tn, tn % NSTAGES);
        cp_commit();

        uint32_t stOff = (uint32_t)((t % NSTAGES) * STAGE_H) * 2u;

        #pragma unroll
        for (int ks = 0; ks < BK / 16; ++ks) {
            uint32_t af[MT][4], bf[NT][2];
            #pragma unroll
            for (int mt = 0; mt < MT; ++mt)
                ldm_x4(af[mt], aLdm + stOff + (uint32_t)(mt * 16 * ASTRIDE + ks * 16) * 2u);
            #pragma unroll
            for (int p = 0; p < 2; ++p) {
                uint32_t bb[4];
                ldm_x4_t(bb, bLdm + stOff + (uint32_t)(ks * 16 * BSTRIDE + p * 16) * 2u);
                bf[2*p    ][0] = bb[0]; bf[2*p    ][1] = bb[1];
                bf[2*p + 1][0] = bb[2]; bf[2*p + 1][1] = bb[3];
            }
            #pragma unroll
            for (int mt = 0; mt < MT; ++mt)
                #pragma unroll
                for (int nt = 0; nt < NT; ++nt)
                    mma_f16(acc[mt][nt], af[mt], bf[nt]);
        }
    }

    // ---- epilogue ----
    #pragma unroll
    for (int mt = 0; mt < MT; ++mt) {
        #pragma unroll
        for (int nt = 0; nt < NT; ++nt) {
            int col = n0 + wn + nt * 8 + tc * 2;
            #pragma unroll
            for (int hrow = 0; hrow < 2; ++hrow) {
                int row  = m0 + wm + mt * 16 + g + hrow * 8;
                float v0 = acc[mt][nt][hrow * 2 + 0];
                float v1 = acc[mt][nt][hrow * 2 + 1];
                size_t off = (size_t)row * ldc + col;
                float r0 = 0.f, r1 = 0.f;
                if (EPI == 2 || EPI == 3) {
                    if (sizeof(RES) == 2) {
                        __half2 rr = *(const __half2*)((const __half*)res + off);
                        r0 = __low2float(rr); r1 = __high2float(rr);
                    } else {
                        float2 rr = *(const float2*)((const float*)res + off);
                        r0 = rr.x; r1 = rr.y;
                    }
                }
                if (EPI == 1) {
                    v0 = gelu_tanh(v0 + bias[col]);
                    v1 = gelu_tanh(v1 + bias[col + 1]);
                } else if (EPI == 2) {
                    v0 = v0 + bias[col]     + r0;
                    v1 = v1 + bias[col + 1] + r1;
                } else if (EPI == 3) {
                    v0 = 2.0f * v0 + r0;
                    v1 = 2.0f * v1 + r1;
                }
                if (sizeof(OUT) == 2) {
                    *(__half2*)((__half*)C + off) = __floats2half2_rn(v0, v1);
                } else {
                    *(float2*)((float*)C + off) = make_float2(v0, v1);
                }
            }
        }
    }
}

// ---------------------------------------------------------------------------
// host launch
// ---------------------------------------------------------------------------
extern "C" void kernel_launch(void* const* d_in, const int* in_sizes, int n_in,
                              void* d_out, int out_size) {
    const float* x   = (const float*)d_in[0];
    const float* wq  = (const float*)d_in[1];
    const float* wk  = (const float*)d_in[2];
    const float* wv  = (const float*)d_in[3];
    const float* wo  = (const float*)d_in[4];
    const float* ln1 = (const float*)d_in[5];
    const float* ln2 = (const float*)d_in[6];
    const float* w1  = (const float*)d_in[7];
    const float* b1  = (const float*)d_in[8];
    const float* w2  = (const float*)d_in[9];
    const float* b2  = (const float*)d_in[10];
    float* out = (float*)d_out;

    __half *x1, *x2, *c, *qkv, *at, *h;
    __half *wqkv, *woh, *w1h, *w2h;
    cudaGetSymbolAddress((void**)&x1,  g_x1);
    cudaGetSymbolAddress((void**)&x2,  g_x2);
    cudaGetSymbolAddress((void**)&c,   g_c);
    cudaGetSymbolAddress((void**)&qkv, g_qkv);
    cudaGetSymbolAddress((void**)&at,  g_at);
    cudaGetSymbolAddress((void**)&h,   g_h);
    cudaGetSymbolAddress((void**)&wqkv, g_wqkv);
    cudaGetSymbolAddress((void**)&woh, g_woh);
    cudaGetSymbolAddress((void**)&w1h, g_w1h);
    cudaGetSymbolAddress((void**)&w2h, g_w2h);

    const int SMG128 = (128 * 72 + 64 * 136) * 3 * 2;   // 107520
    const int SMG256 = (256 * 72 + 64 * 136) * 3 * 2;   // 162816
    const int SMFA   = FA_SMEM_H * 2;                    // 92160

    static bool init_done = false;
    static cudaStream_t s2, s3;
    static cudaEvent_t evFork, evJoin, evFork3, evJoin3;
    if (!init_done) {
        cudaFuncSetAttribute(gemm_kernel<128,0,__half,float >, cudaFuncAttributeMaxDynamicSharedMemorySize, SMG128);
        cudaFuncSetAttribute(gemm_kernel<256,1,__half,float >, cudaFuncAttributeMaxDynamicSharedMemorySize, SMG256);
        cudaFuncSetAttribute(gemm_kernel<128,2,__half,__half>, cudaFuncAttributeMaxDynamicSharedMemorySize, SMG128);
        cudaFuncSetAttribute(gemm_kernel<128,2,float ,__half>, cudaFuncAttributeMaxDynamicSharedMemorySize, SMG128);
        cudaFuncSetAttribute(gemm_kernel<128,3,__half,float >, cudaFuncAttributeMaxDynamicSharedMemorySize, SMG128);
        cudaFuncSetAttribute(flash_kernel, cudaFuncAttributeMaxDynamicSharedMemorySize, SMFA);
        cudaStreamCreateWithFlags(&s2, cudaStreamNonBlocking);
        cudaStreamCreateWithFlags(&s3, cudaStreamNonBlocking);
        cudaEventCreateWithFlags(&evFork,  cudaEventDisableTiming);
        cudaEventCreateWithFlags(&evJoin,  cudaEventDisableTiming);
        cudaEventCreateWithFlags(&evFork3, cudaEventDisableTiming);
        cudaEventCreateWithFlags(&evJoin3, cudaEventDisableTiming);
        init_done = true;
    }

    // launch #1: qkv weight cvt (main stream)
    cvt_qkv<<<(DMODEL*DMODEL/4 + 255)/256, 256>>>(wq, wk, wv, wqkv);

    // fork s2: wo/w1/w2 conversion
    cudaEventRecord(evFork, 0);
    cudaStreamWaitEvent(s2, evFork, 0);
    cvt_h<<<(DMODEL*DMODEL/4 + 255)/256, 256, 0, s2>>>(wo, woh, DMODEL*DMODEL/4);
    cvt_h<<<(DMODEL*FFDIM/4  + 255)/256, 256, 0, s2>>>(w1, w1h, DMODEL*FFDIM/4);
    cvt_h<<<(DMODEL*FFDIM/4  + 255)/256, 256, 0, s2>>>(w2, w2h, DMODEL*FFDIM/4);
    cudaEventRecord(evJoin, s2);

    // fork s3: LN1
    cudaEventRecord(evFork3, 0);
    cudaStreamWaitEvent(s3, evFork3, 0);
    ln_kernel<float><<<ROWS / 8, 256, 0, s3>>>(x, ln1, c);
    cudaEventRecord(evJoin3, s3);

    // main stream
    cudaStreamWaitEvent(0, evJoin3, 0);
    dim3 gQKV(QKVLD / 128, ROWS / 128, 1);            // (24, 64)
    gemm_kernel<128,0,__half,float><<<gQKV,256,SMG128>>>(c,DMODEL, wqkv,QKVLD, qkv,QKVLD, nullptr,(const float*)nullptr, DMODEL);

    flash_kernel<<<dim3(SEQ/128, BATCH*NHEAD), 256, SMFA>>>(qkv, at);

    cudaStreamWaitEvent(0, evJoin, 0);

    // 6. x1 = x + 2*(at @ wo)
    dim3 gA(DMODEL / 128, ROWS / 128, 1);             // (8, 64)
    gemm_kernel<128,3,__half,float><<<gA,256,SMG128>>>(at,DMODEL, woh,DMODEL, x1,DMODEL, nullptr, x, DMODEL);

    // 7-9. MLP #1  (FF1 uses BM=256: grid (32,32), 512 thr)
    ln_kernel<__half><<<ROWS / 8, 256>>>(x1, ln2, c);
    dim3 gF(FFDIM / 128, ROWS / 256, 1);              // (32, 32)
    gemm_kernel<256,1,__half,float ><<<gF,512,SMG256>>>(c,DMODEL, w1h,FFDIM, h,FFDIM, b1, (const float*)nullptr, DMODEL);
    gemm_kernel<128,2,__half,__half><<<gA,256,SMG128>>>(h,FFDIM, w2h,DMODEL, x2,DMODEL, b2, x1, FFDIM);

    // 10-12. MLP #2
    ln_kernel<__half><<<ROWS / 8, 256>>>(x2, ln2, c);
    gemm_kernel<256,1,__half,float ><<<gF,512,SMG256>>>(c,DMODEL, w1h,FFDIM, h,FFDIM, b1, (const float*)nullptr, DMODEL);
    gemm_kernel<128,2,float ,__half><<<gA,256,SMG128>>>(h,FFDIM, w2h,DMODEL, out,DMODEL, b2, x2, FFDIM);
}

// round 17
// speedup vs baseline: 1.0336x; 1.0336x over previous
#include <cuda_runtime.h>
#include <cuda_fp16.h>
#include <math.h>
#include <stdint.h>

// ---------------------------------------------------------------------------
// Transformer block: B=16, S=512, D=1024, H=16, HD=64, FF=4096
// FP16 mma.sync.m16n8k16 + ldmatrix.x4 (.trans for B), fp32 accumulate,
// BK=64 / 3-stage cp.async GEMM (BM=128, 2 CTA/SM), fused QKV,
// natural [K,N] weights, flash attention (exp2 softmax), side-stream
// prologue, half residual spine, warp-per-row LN, MUFU.TANH gelu.
// ---------------------------------------------------------------------------

#define BATCH   16
#define SEQ     512
#define DMODEL  1024
#define NHEAD   16
#define HDIM    64
#define FFDIM   4096
#define ROWS    (BATCH * SEQ)          // 8192
#define QKVLD   (3 * DMODEL)           // 3072

// half residual spine
__device__ __half g_x1 [ROWS * DMODEL];
__device__ __half g_x2 [ROWS * DMODEL];
// half operands
__device__ __half g_c   [ROWS * DMODEL];
__device__ __half g_qkv [(size_t)ROWS * QKVLD];
__device__ __half g_at  [ROWS * DMODEL];
__device__ __half g_h   [ROWS * FFDIM];
// half weights (natural [K,N] layout)
__device__ __half g_wqkv[(size_t)DMODEL * QKVLD];            // wq*0.125*log2e | wk | wv
__device__ __half g_woh [DMODEL * DMODEL];
__device__ __half g_w1h [(size_t)DMODEL * FFDIM];
__device__ __half g_w2h [(size_t)DMODEL * FFDIM];

// ---------------------------------------------------------------------------
__device__ __forceinline__ float tanh_fast(float x) {
    float r;
    asm("tanh.approx.f32 %0, %1;" : "=f"(r) : "f"(x));
    return r;
}
__device__ __forceinline__ float exp2_fast(float x) {
    float r;
    asm("ex2.approx.f32 %0, %1;" : "=f"(r) : "f"(x));
    return r;
}

__device__ __forceinline__ float gelu_tanh(float x) {
    float x3 = x * x * x;
    float u  = 0.7978845608028654f * (x + 0.044715f * x3);
    return 0.5f * x * (1.0f + tanh_fast(u));
}

__device__ __forceinline__ void mma_f16(float* c, const uint32_t* a, const uint32_t* b) {
    asm volatile(
        "mma.sync.aligned.m16n8k16.row.col.f32.f16.f16.f32 "
        "{%0,%1,%2,%3}, {%4,%5,%6,%7}, {%8,%9}, {%0,%1,%2,%3};\n"
        : "+f"(c[0]), "+f"(c[1]), "+f"(c[2]), "+f"(c[3])
        : "r"(a[0]), "r"(a[1]), "r"(a[2]), "r"(a[3]),
          "r"(b[0]), "r"(b[1]));
}

__device__ __forceinline__ void ldm_x4(uint32_t* r, uint32_t addr) {
    asm volatile(
        "ldmatrix.sync.aligned.m8n8.x4.shared.b16 {%0,%1,%2,%3}, [%4];"
        : "=r"(r[0]), "=r"(r[1]), "=r"(r[2]), "=r"(r[3]) : "r"(addr));
}
__device__ __forceinline__ void ldm_x4_t(uint32_t* r, uint32_t addr) {
    asm volatile(
        "ldmatrix.sync.aligned.m8n8.x4.trans.shared.b16 {%0,%1,%2,%3}, [%4];"
        : "=r"(r[0]), "=r"(r[1]), "=r"(r[2]), "=r"(r[3]) : "r"(addr));
}

__device__ __forceinline__ void cp16(uint32_t dst, const void* src) {
    asm volatile("cp.async.cg.shared.global [%0], [%1], 16;\n" :: "r"(dst), "l"(src));
}
__device__ __forceinline__ void cp_commit() {
    asm volatile("cp.async.commit_group;\n");
}
template<int N>
__device__ __forceinline__ void cp_wait() {
    asm volatile("cp.async.wait_group %0;\n" :: "n"(N));
}

__device__ __forceinline__ uint32_t packh2(float a, float b) {
    __half2 h = __floats2half2_rn(a, b);
    return *(uint32_t*)&h;
}

__device__ __forceinline__ float4 load4(const float* p, int idx) {
    return ((const float4*)p)[idx];
}
__device__ __forceinline__ float4 load4(const __half* p, int idx) {
    __half2 a = ((const __half2*)p)[idx * 2];
    __half2 b = ((const __half2*)p)[idx * 2 + 1];
    return make_float4(__low2float(a), __high2float(a),
                       __low2float(b), __high2float(b));
}

// ---------------------------------------------------------------------------
// cvt: fp32 -> fp16 straight copy
// ---------------------------------------------------------------------------
__global__ void cvt_h(const float* __restrict__ in, __half* __restrict__ out, int n4) {
    int i = blockIdx.x * blockDim.x + threadIdx.x;
    if (i < n4) {
        float4 v = ((const float4*)in)[i];
        ((__half2*)out)[i * 2]     = __floats2half2_rn(v.x, v.y);
        ((__half2*)out)[i * 2 + 1] = __floats2half2_rn(v.z, v.w);
    }
}

// cvt QKV: interleave wq*(0.125*log2e)|wk|wv into [K=1024, N=3072]
#define QSCALE (0.125f * 1.44269504088896341f)
__global__ void cvt_qkv(const float* __restrict__ wq, const float* __restrict__ wk,
                        const float* __restrict__ wv, __half* __restrict__ out) {
    int i = blockIdx.x * blockDim.x + threadIdx.x;
    int row = i >> 8;
    int c4  = i & 255;
    float4 a = ((const float4*)wq)[i];
    float4 b = ((const float4*)wk)[i];
    float4 c = ((const float4*)wv)[i];
    __half2* o = (__half2*)(out + (size_t)row * QKVLD);
    o[c4 * 2]            = __floats2half2_rn(a.x * QSCALE, a.y * QSCALE);
    o[c4 * 2 + 1]        = __floats2half2_rn(a.z * QSCALE, a.w * QSCALE);
    o[512 + c4 * 2]      = __floats2half2_rn(b.x, b.y);
    o[512 + c4 * 2 + 1]  = __floats2half2_rn(b.z, b.w);
    o[1024 + c4 * 2]     = __floats2half2_rn(c.x, c.y);
    o[1024 + c4 * 2 + 1] = __floats2half2_rn(c.z, c.w);
}

// ---------------------------------------------------------------------------
// LayerNorm, warp-per-row (8 rows/block, shfl-only). TIN float or half.
// ---------------------------------------------------------------------------
template<typename TIN>
__global__ void ln_kernel(const TIN* __restrict__ x,
                          const float* __restrict__ scale,
                          __half* __restrict__ out) {
    int warp = threadIdx.x >> 5, lane = threadIdx.x & 31;
    int row  = blockIdx.x * 8 + warp;
    const TIN* xr = x + (size_t)row * DMODEL;

    float4 v[8];
    float s = 0.f, q = 0.f;
    #pragma unroll
    for (int j = 0; j < 8; j++) {
        v[j] = load4(xr + j * 128, lane);
        s += v[j].x + v[j].y + v[j].z + v[j].w;
        q += v[j].x * v[j].x + v[j].y * v[j].y + v[j].z * v[j].z + v[j].w * v[j].w;
    }
    #pragma unroll
    for (int o = 16; o > 0; o >>= 1) {
        s += __shfl_xor_sync(0xffffffffu, s, o);
        q += __shfl_xor_sync(0xffffffffu, q, o);
    }
    float mean = s * (1.0f / DMODEL);
    float var  = q * (1.0f / DMODEL) - mean * mean;
    float r    = rsqrtf(var + 1e-6f);

    __half* orow = out + (size_t)row * DMODEL;
    #pragma unroll
    for (int j = 0; j < 8; j++) {
        float4 sc = ((const float4*)scale)[j * 32 + lane];
        __half2 o0 = __floats2half2_rn((v[j].x - mean) * r * sc.x, (v[j].y - mean) * r * sc.y);
        __half2 o1 = __floats2half2_rn((v[j].z - mean) * r * sc.z, (v[j].w - mean) * r * sc.w);
        __half2* op = (__half2*)(orow + j * 128 + lane * 4);
        op[0] = o0; op[1] = o1;
    }
}

// ---------------------------------------------------------------------------
// Fused flash attention, double-buffered K/V, exp2-domain softmax.
// grid = (S/128, B*H), 256 threads, 2 CTA/SM; q pre-scaled by 0.125*log2e.
// ---------------------------------------------------------------------------
#define QS_STRIDE 72
#define KS_STRIDE 72
#define VS_STRIDE 72
#define CHUNK     128
#define FA_SMEM_H (128 * QS_STRIDE + 2 * 2 * CHUNK * KS_STRIDE)

__global__ void __launch_bounds__(256, 2)
flash_kernel(const __half* __restrict__ qkv, __half* __restrict__ at) {
    extern __shared__ __half sm[];
    __half* Qs = sm;
    __half* KVs = Qs + 128 * QS_STRIDE;

    int bh = blockIdx.y;
    int b  = bh >> 4;
    int h  = bh & 15;
    int i0 = blockIdx.x * 128;

    const __half* Qg = qkv + ((size_t)(b * SEQ + i0)) * QKVLD + h * HDIM;
    const __half* Kg = qkv + ((size_t)(b * SEQ))      * QKVLD + DMODEL     + h * HDIM;
    const __half* Vg = qkv + ((size_t)(b * SEQ))      * QKVLD + 2 * DMODEL + h * HDIM;

    int tid = threadIdx.x;
    uint32_t Qsb  = (uint32_t)__cvta_generic_to_shared(Qs);
    uint32_t KVsb = (uint32_t)__cvta_generic_to_shared(KVs);
    const uint32_t STAGE_B = (uint32_t)(2 * CHUNK * KS_STRIDE) * 2u;
    const uint32_t VOFF_B  = (uint32_t)(CHUNK * KS_STRIDE) * 2u;

    auto load_chunk = [&](int jc, int stg) {
        const __half* Kc = Kg + (size_t)(jc * CHUNK) * QKVLD;
        const __half* Vc = Vg + (size_t)(jc * CHUNK) * QKVLD;
        uint32_t base = KVsb + (uint32_t)stg * STAGE_B;
        #pragma unroll
        for (int i = 0; i < 4; i++) {
            int idx = tid + i * 256;
            int r = idx >> 3, c = idx & 7;
            cp16(base + (uint32_t)(r * KS_STRIDE + c * 8) * 2u, Kc + (size_t)r * QKVLD + c * 8);
        }
        #pragma unroll
        for (int i = 0; i < 4; i++) {
            int idx = tid + i * 256;
            int r = idx >> 3, c = idx & 7;
            cp16(base + VOFF_B + (uint32_t)(r * VS_STRIDE + c * 8) * 2u, Vc + (size_t)r * QKVLD + c * 8);
        }
    };

    #pragma unroll
    for (int i = 0; i < 4; i++) {
        int idx = tid + i * 256;
        int r = idx >> 3, c = idx & 7;
        cp16(Qsb + (uint32_t)(r * QS_STRIDE + c * 8) * 2u, Qg + (size_t)r * QKVLD + c * 8);
    }
    load_chunk(0, 0);
    cp_commit();

    int warp = tid >> 5, lane = tid & 31;
    int g = lane >> 2, tc = lane & 3;
    int wr = warp * 16;
    int lane16 = lane & 15, laneHi = lane >> 4;
    int bRow   = laneHi * 8 + (lane & 7);
    int bKoff  = ((lane >> 3) & 1) * 8;
    int tRow   = (lane & 7) + ((lane >> 3) & 1) * 8;
    int tNoff  = laneHi * 8;

    uint32_t qLdm  = Qsb  + (uint32_t)((wr + lane16) * QS_STRIDE + laneHi * 8) * 2u;
    uint32_t kLdm0 = KVsb + (uint32_t)(bRow * KS_STRIDE + bKoff) * 2u;
    uint32_t vLdm0 = KVsb + VOFF_B + (uint32_t)(tRow * VS_STRIDE + tNoff) * 2u;

    float m0 = -1e30f, m1 = -1e30f, l0 = 0.f, l1 = 0.f;
    float O[8][4];
    #pragma unroll
    for (int dt = 0; dt < 8; dt++)
        #pragma unroll
        for (int e = 0; e < 4; e++) O[dt][e] = 0.f;

    #pragma unroll
    for (int jc = 0; jc < 4; jc++) {
        if (jc < 3) { load_chunk(jc + 1, (jc + 1) & 1); }
        cp_commit();
        if (jc < 3) cp_wait<1>(); else cp_wait<0>();
        __syncthreads();

        uint32_t stOff = (uint32_t)(jc & 1) * STAGE_B;
        uint32_t kLdm = kLdm0 + stOff;
        uint32_t vLdm = vLdm0 + stOff;

        float S[16][4];
        #pragma unroll
        for (int nt = 0; nt < 16; nt++)
            #pragma unroll
            for (int e = 0; e < 4; e++) S[nt][e] = 0.f;

        #pragma unroll
        for (int ks = 0; ks < 4; ks++) {
            uint32_t a[4];
            ldm_x4(a, qLdm + (uint32_t)(ks * 16) * 2u);
            #pragma unroll
            for (int p = 0; p < 8; p++) {
                uint32_t bb[4];
                ldm_x4(bb, kLdm + (uint32_t)((p * 16) * KS_STRIDE + ks * 16) * 2u);
                mma_f16(S[2*p    ], a, bb);
                mma_f16(S[2*p + 1], a, bb + 2);
            }
        }

        // online softmax (log2 domain)
        float mx0 = -1e30f, mx1 = -1e30f;
        #pragma unroll
        for (int nt = 0; nt < 16; nt++) {
            mx0 = fmaxf(mx0, fmaxf(S[nt][0], S[nt][1]));
            mx1 = fmaxf(mx1, fmaxf(S[nt][2], S[nt][3]));
        }
        mx0 = fmaxf(mx0, __shfl_xor_sync(0xffffffffu, mx0, 1));
        mx0 = fmaxf(mx0, __shfl_xor_sync(0xffffffffu, mx0, 2));
        mx1 = fmaxf(mx1, __shfl_xor_sync(0xffffffffu, mx1, 1));
        mx1 = fmaxf(mx1, __shfl_xor_sync(0xffffffffu, mx1, 2));
        float mn0 = fmaxf(m0, mx0), mn1 = fmaxf(m1, mx1);
        float al0 = exp2_fast(m0 - mn0), al1 = exp2_fast(m1 - mn1);
        m0 = mn0; m1 = mn1;

        float rs0 = 0.f, rs1 = 0.f;
        #pragma unroll
        for (int nt = 0; nt < 16; nt++) {
            S[nt][0] = exp2_fast(S[nt][0] - mn0);
            S[nt][1] = exp2_fast(S[nt][1] - mn0);
            S[nt][2] = exp2_fast(S[nt][2] - mn1);
            S[nt][3] = exp2_fast(S[nt][3] - mn1);
            rs0 += S[nt][0] + S[nt][1];
            rs1 += S[nt][2] + S[nt][3];
        }
        rs0 += __shfl_xor_sync(0xffffffffu, rs0, 1);
        rs0 += __shfl_xor_sync(0xffffffffu, rs0, 2);
        rs1 += __shfl_xor_sync(0xffffffffu, rs1, 1);
        rs1 += __shfl_xor_sync(0xffffffffu, rs1, 2);
        l0 = l0 * al0 + rs0;
        l1 = l1 * al1 + rs1;

        #pragma unroll
        for (int dt = 0; dt < 8; dt++) {
            O[dt][0] *= al0; O[dt][1] *= al0;
            O[dt][2] *= al1; O[dt][3] *= al1;
        }

        #pragma unroll
        for (int kp = 0; kp < 8; kp++) {
            uint32_t a[4];
            a[0] = packh2(S[2*kp  ][0], S[2*kp  ][1]);
            a[1] = packh2(S[2*kp  ][2], S[2*kp  ][3]);
            a[2] = packh2(S[2*kp+1][0], S[2*kp+1][1]);
            a[3] = packh2(S[2*kp+1][2], S[2*kp+1][3]);
            #pragma unroll
            for (int p = 0; p < 4; p++) {
                uint32_t bb[4];
                ldm_x4_t(bb, vLdm + (uint32_t)((kp * 16) * VS_STRIDE + p * 16) * 2u);
                mma_f16(O[2*p    ], a, bb);
                mma_f16(O[2*p + 1], a, bb + 2);
            }
        }
        __syncthreads();
    }

    float inv0 = 1.0f / l0, inv1 = 1.0f / l1;
    int row0 = b * SEQ + i0 + wr + g;
    __half* ob = at + (size_t)row0 * DMODEL + h * HDIM;
    #pragma unroll
    for (int dt = 0; dt < 8; dt++) {
        __half2 o0 = __floats2half2_rn(O[dt][0] * inv0, O[dt][1] * inv0);
        __half2 o1 = __floats2half2_rn(O[dt][2] * inv1, O[dt][3] * inv1);
        *(__half2*)(ob + dt * 8 + tc * 2)                        = o0;
        *(__half2*)(ob + (size_t)8 * DMODEL + dt * 8 + tc * 2)   = o1;
    }
}

// ---------------------------------------------------------------------------
// FP16 GEMM, fp32 accumulate, BK=64 / 3-stage cp.async, ldmatrix(.trans B).
// BM=128, BN=128, 256 threads (8 warps: 2M x 4N), 2 CTA/SM.
// EPI: 0 none | 1 gelu(acc+bias) | 2 acc+bias+res | 3 res+2*acc
// ---------------------------------------------------------------------------
template<int EPI, typename OUT, typename RES>
__global__ void __launch_bounds__(256, 2)
gemm_kernel(const __half* __restrict__ A, int lda,
            const __half* __restrict__ B, int ldb,
            OUT* __restrict__ C, int ldc,
            const float* __restrict__ bias,
            const RES* __restrict__ res,
            int K) {
    constexpr int BM = 128, BN = 128, BK = 64;
    constexpr int NSTAGES = 3;
    constexpr int MT = 4, NT = 4;
    constexpr int ASTRIDE = BK + 8;
    constexpr int BSTRIDE = BN + 8;
    constexpr int A_H = BM * ASTRIDE;
    constexpr int B_H = BK * BSTRIDE;
    constexpr int STAGE_H = A_H + B_H;

    extern __shared__ __half smem[];
    uint32_t smem_u32 = (uint32_t)__cvta_generic_to_shared(smem);

    int m0 = blockIdx.y * BM;
    int n0 = blockIdx.x * BN;

    int tid  = threadIdx.x;
    int warp = tid >> 5, lane = tid & 31;
    int wm = (warp & 1) * 64;
    int wn = (warp >> 1) * 32;
    int g  = lane >> 2, tc = lane & 3;
    int lane16 = lane & 15, laneHi = lane >> 4;
    int tRow   = (lane & 7) + ((lane >> 3) & 1) * 8;
    int tNoff  = laneHi * 8;

    uint32_t aLdm = smem_u32 + (uint32_t)((wm + lane16) * ASTRIDE + laneHi * 8) * 2u;
    uint32_t bLdm = smem_u32 + (uint32_t)A_H * 2u
                  + (uint32_t)(tRow * BSTRIDE + wn + tNoff) * 2u;

    int a_r  = tid >> 3;
    int a_k8 = (tid & 7) * 8;
    int b_r  = tid >> 4;
    int b_c8 = (tid & 15) * 8;
    const __half* Aptr = A + (size_t)(m0 + a_r) * lda + a_k8;
    const __half* Bptr = B + (size_t)b_r * ldb + n0 + b_c8;

    float acc[MT][NT][4];
    #pragma unroll
    for (int i = 0; i < MT; i++)
        #pragma unroll
        for (int j = 0; j < NT; j++)
            #pragma unroll
            for (int e = 0; e < 4; e++) acc[i][j][e] = 0.f;

    const int ntiles = K / BK;

    auto load_tile = [&](int t, int s) {
        int kt = t * BK;
        uint32_t aBase = smem_u32 + (uint32_t)(s * STAGE_H) * 2u;
        uint32_t bBase = aBase + (uint32_t)A_H * 2u;
        #pragma unroll
        for (int i = 0; i < 4; ++i)
            cp16(aBase + (uint32_t)((a_r + i * 32) * ASTRIDE + a_k8) * 2u,
                 Aptr + (size_t)(i * 32) * lda + kt);
        #pragma unroll
        for (int i = 0; i < 4; ++i)
            cp16(bBase + (uint32_t)((b_r + i * 16) * BSTRIDE + b_c8) * 2u,
                 Bptr + (size_t)(kt + i * 16) * ldb);
    };

    #pragma unroll
    for (int s = 0; s < NSTAGES - 1; ++s) {
        if (s < ntiles) load_tile(s, s);
        cp_commit();
    }

    for (int t = 0; t < ntiles; ++t) {
        cp_wait<NSTAGES - 2>();
        __syncthreads();

        int tn = t + NSTAGES - 1;
        if (tn < ntiles) load_tile(tn, tn % NSTAGES);
        cp_commit();

        uint32_t stOff = (uint32_t)((t % NSTAGES) * STAGE_H) * 2u;

        #pragma unroll
        for (int ks = 0; ks < BK / 16; ++ks) {
            uint32_t af[MT][4], bf[NT][2];
            #pragma unroll
            for (int mt = 0; mt < MT; ++mt)
                ldm_x4(af[mt], aLdm + stOff + (uint32_t)(mt * 16 * ASTRIDE + ks * 16) * 2u);
            #pragma unroll
            for (int p = 0; p < 2; ++p) {
                uint32_t bb[4];
                ldm_x4_t(bb, bLdm + stOff + (uint32_t)(ks * 16 * BSTRIDE + p * 16) * 2u);
                bf[2*p    ][0] = bb[0]; bf[2*p    ][1] = bb[1];
                bf[2*p + 1][0] = bb[2]; bf[2*p + 1][1] = bb[3];
            }
            #pragma unroll
            for (int mt = 0; mt < MT; ++mt)
                #pragma unroll
                for (int nt = 0; nt < NT; ++nt)
                    mma_f16(acc[mt][nt], af[mt], bf[nt]);
        }
    }

    // ---- epilogue ----
    #pragma unroll
    for (int mt = 0; mt < MT; ++mt) {
        #pragma unroll
        for (int nt = 0; nt < NT; ++nt) {
            int col = n0 + wn + nt * 8 + tc * 2;
            #pragma unroll
            for (int hrow = 0; hrow < 2; ++hrow) {
                int row  = m0 + wm + mt * 16 + g + hrow * 8;
                float v0 = acc[mt][nt][hrow * 2 + 0];
                float v1 = acc[mt][nt][hrow * 2 + 1];
                size_t off = (size_t)row * ldc + col;
                float r0 = 0.f, r1 = 0.f;
                if (EPI == 2 || EPI == 3) {
                    if (sizeof(RES) == 2) {
                        __half2 rr = *(const __half2*)((const __half*)res + off);
                        r0 = __low2float(rr); r1 = __high2float(rr);
                    } else {
                        float2 rr = *(const float2*)((const float*)res + off);
                        r0 = rr.x; r1 = rr.y;
                    }
                }
                if (EPI == 1) {
                    v0 = gelu_tanh(v0 + bias[col]);
                    v1 = gelu_tanh(v1 + bias[col + 1]);
                } else if (EPI == 2) {
                    v0 = v0 + bias[col]     + r0;
                    v1 = v1 + bias[col + 1] + r1;
                } else if (EPI == 3) {
                    v0 = 2.0f * v0 + r0;
                    v1 = 2.0f * v1 + r1;
                }
                if (sizeof(OUT) == 2) {
                    *(__half2*)((__half*)C + off) = __floats2half2_rn(v0, v1);
                } else {
                    *(float2*)((float*)C + off) = make_float2(v0, v1);
                }
            }
        }
    }
}

// ---------------------------------------------------------------------------
// host launch
// ---------------------------------------------------------------------------
extern "C" void kernel_launch(void* const* d_in, const int* in_sizes, int n_in,
                              void* d_out, int out_size) {
    const float* x   = (const float*)d_in[0];
    const float* wq  = (const float*)d_in[1];
    const float* wk  = (const float*)d_in[2];
    const float* wv  = (const float*)d_in[3];
    const float* wo  = (const float*)d_in[4];
    const float* ln1 = (const float*)d_in[5];
    const float* ln2 = (const float*)d_in[6];
    const float* w1  = (const float*)d_in[7];
    const float* b1  = (const float*)d_in[8];
    const float* w2  = (const float*)d_in[9];
    const float* b2  = (const float*)d_in[10];
    float* out = (float*)d_out;

    __half *x1, *x2, *c, *qkv, *at, *h;
    __half *wqkv, *woh, *w1h, *w2h;
    cudaGetSymbolAddress((void**)&x1,  g_x1);
    cudaGetSymbolAddress((void**)&x2,  g_x2);
    cudaGetSymbolAddress((void**)&c,   g_c);
    cudaGetSymbolAddress((void**)&qkv, g_qkv);
    cudaGetSymbolAddress((void**)&at,  g_at);
    cudaGetSymbolAddress((void**)&h,   g_h);
    cudaGetSymbolAddress((void**)&wqkv, g_wqkv);
    cudaGetSymbolAddress((void**)&woh, g_woh);
    cudaGetSymbolAddress((void**)&w1h, g_w1h);
    cudaGetSymbolAddress((void**)&w2h, g_w2h);

    const int SMG  = (128 * 72 + 64 * 136) * 3 * 2;   // 107520
    const int SMFA = FA_SMEM_H * 2;                    // 92160

    static bool init_done = false;
    static cudaStream_t s2, s3;
    static cudaEvent_t evFork, evJoin, evFork3, evJoin3;
    if (!init_done) {
        cudaFuncSetAttribute(gemm_kernel<0,__half,float >, cudaFuncAttributeMaxDynamicSharedMemorySize, SMG);
        cudaFuncSetAttribute(gemm_kernel<1,__half,float >, cudaFuncAttributeMaxDynamicSharedMemorySize, SMG);
        cudaFuncSetAttribute(gemm_kernel<2,__half,__half>, cudaFuncAttributeMaxDynamicSharedMemorySize, SMG);
        cudaFuncSetAttribute(gemm_kernel<2,float ,__half>, cudaFuncAttributeMaxDynamicSharedMemorySize, SMG);
        cudaFuncSetAttribute(gemm_kernel<3,__half,float >, cudaFuncAttributeMaxDynamicSharedMemorySize, SMG);
        cudaFuncSetAttribute(flash_kernel, cudaFuncAttributeMaxDynamicSharedMemorySize, SMFA);
        cudaStreamCreateWithFlags(&s2, cudaStreamNonBlocking);
        cudaStreamCreateWithFlags(&s3, cudaStreamNonBlocking);
        cudaEventCreateWithFlags(&evFork,  cudaEventDisableTiming);
        cudaEventCreateWithFlags(&evJoin,  cudaEventDisableTiming);
        cudaEventCreateWithFlags(&evFork3, cudaEventDisableTiming);
        cudaEventCreateWithFlags(&evJoin3, cudaEventDisableTiming);
        init_done = true;
    }

    // launch #1: qkv weight cvt (main stream)
    cvt_qkv<<<(DMODEL*DMODEL/4 + 255)/256, 256>>>(wq, wk, wv, wqkv);

    // fork s2: wo/w1/w2 conversion
    cudaEventRecord(evFork, 0);
    cudaStreamWaitEvent(s2, evFork, 0);
    cvt_h<<<(DMODEL*DMODEL/4 + 255)/256, 256, 0, s2>>>(wo, woh, DMODEL*DMODEL/4);
    cvt_h<<<(DMODEL*FFDIM/4  + 255)/256, 256, 0, s2>>>(w1, w1h, DMODEL*FFDIM/4);
    cvt_h<<<(DMODEL*FFDIM/4  + 255)/256, 256, 0, s2>>>(w2, w2h, DMODEL*FFDIM/4);
    cudaEventRecord(evJoin, s2);

    // fork s3: LN1
    cudaEventRecord(evFork3, 0);
    cudaStreamWaitEvent(s3, evFork3, 0);
    ln_kernel<float><<<ROWS / 8, 256, 0, s3>>>(x, ln1, c);
    cudaEventRecord(evJoin3, s3);

    // main stream
    cudaStreamWaitEvent(0, evJoin3, 0);
    dim3 gQKV(QKVLD / 128, ROWS / 128, 1);            // (24, 64)
    gemm_kernel<0,__half,float><<<gQKV,256,SMG>>>(c,DMODEL, wqkv,QKVLD, qkv,QKVLD, nullptr,(const float*)nullptr, DMODEL);

    flash_kernel<<<dim3(SEQ/128, BATCH*NHEAD), 256, SMFA>>>(qkv, at);

    cudaStreamWaitEvent(0, evJoin, 0);

    // 6. x1 = x + 2*(at @ wo)
    dim3 gA(DMODEL / 128, ROWS / 128, 1);             // (8, 64)
    gemm_kernel<3,__half,float><<<gA,256,SMG>>>(at,DMODEL, woh,DMODEL, x1,DMODEL, nullptr, x, DMODEL);

    // 7-9. MLP #1
    ln_kernel<__half><<<ROWS / 8, 256>>>(x1, ln2, c);
    dim3 gF(FFDIM / 128, ROWS / 128, 1);              // (32, 64)
    gemm_kernel<1,__half,float ><<<gF,256,SMG>>>(c,DMODEL, w1h,FFDIM, h,FFDIM, b1, (const float*)nullptr, DMODEL);
    gemm_kernel<2,__half,__half><<<gA,256,SMG>>>(h,FFDIM, w2h,DMODEL, x2,DMODEL, b2, x1, FFDIM);

    // 10-12. MLP #2
    ln_kernel<__half><<<ROWS / 8, 256>>>(x2, ln2, c);
    gemm_kernel<1,__half,float ><<<gF,256,SMG>>>(c,DMODEL, w1h,FFDIM, h,FFDIM, b1, (const float*)nullptr, DMODEL);
    gemm_kernel<2,float ,__half><<<gA,256,SMG>>>(h,FFDIM, w2h,DMODEL, out,DMODEL, b2, x2, FFDIM);
}